// round 4
// baseline (speedup 1.0000x reference)
#include <cuda_runtime.h>
#include <math.h>

// Problem constants (shapes fixed by the dataset)
#define B_IN  8
#define C_IN  16
#define H_IN  128
#define W_IN  128
#define HO    127
#define WO    127

// Tile geometry: 16x16 output tile -> 17x17 input halo
#define TW    16
#define TH    16
#define IW    17
#define NPIX  (IW * IW)   // 289

// 11 knot intervals x 4 out-features(e) x 4 cardinal bases
__device__ float d_W[11 * 16];
__device__ float d_bw[4];
__device__ float d_grid0;
__device__ float d_invh;

// -----------------------------------------------------------------------------
// Prep: build the per-interval weight table from the (tiny) parameter tensors.
//   W[i][e][m] = (0 <= i-3+m < 8) ? spline_weight[e][i-3+m] * spline_scaler[e] : 0
// On the uniform, unclamped knot grid the cubic Cox-de-Boor bases are exactly
// the cardinal cubic B-spline translates; the reference merely drops basis
// indices outside [0,8), which we fold into zeros in this table.
// -----------------------------------------------------------------------------
__global__ void kan_prep(const float* __restrict__ base_weight,
                         const float* __restrict__ spline_weight,
                         const float* __restrict__ spline_scaler,
                         const float* __restrict__ grid) {
    int t = threadIdx.x;
    if (t == 0) {
        d_grid0 = grid[0];
        d_invh  = 1.0f / (grid[1] - grid[0]);
    }
    if (t < 4) d_bw[t] = base_weight[t];
    if (t < 176) {
        int m = t & 3;
        int e = (t >> 2) & 3;
        int i = t >> 4;          // 0..10
        int j = i - 3 + m;       // global basis index
        float w = 0.0f;
        if (j >= 0 && j < 8) w = spline_weight[e * 8 + j] * spline_scaler[e];
        d_W[t] = w;
    }
}

// -----------------------------------------------------------------------------
// Per-value evaluation: accumulate silu-sum and 4 spline sums (over channels).
// -----------------------------------------------------------------------------
struct Acc {
    float ss;            // sum of silu(v) over channels
    float a0, a1, a2, a3;// sum of spline_e(v) over channels, e = 0..3
};

__device__ __forceinline__ void eval_accum(float v, float g0, float invh,
                                           const float* __restrict__ sW, Acc& A) {
    // SiLU
    float s = __fdividef(v, 1.0f + __expf(-v));
    A.ss += s;

    // Uniform cubic B-spline: interval + local fraction
    float u  = (v - g0) * invh;
    float fi = floorf(u);
    float f  = u - fi;
    int   i  = (int)fi;
    bool  ok = (u >= 0.0f) && (u < 11.0f);
    if (!ok) i = 0;
    float valid = ok ? 1.0f : 0.0f;

    float f2  = f * f;
    float f3  = f2 * f;
    float omf = 1.0f - f;
    float N0  = valid * (omf * omf * omf) * (1.0f / 6.0f);
    float N1  = valid * (0.5f * f3 - f2 + (2.0f / 3.0f));
    float N2  = valid * (-0.5f * f3 + 0.5f * f2 + 0.5f * f + (1.0f / 6.0f));
    float N3  = valid * f3 * (1.0f / 6.0f);

    const float4* Wi = reinterpret_cast<const float4*>(sW + i * 16);
    float4 w0 = Wi[0];
    float4 w1 = Wi[1];
    float4 w2 = Wi[2];
    float4 w3 = Wi[3];
    A.a0 += N0 * w0.x + N1 * w0.y + N2 * w0.z + N3 * w0.w;
    A.a1 += N0 * w1.x + N1 * w1.y + N2 * w1.z + N3 * w1.w;
    A.a2 += N0 * w2.x + N1 * w2.y + N2 * w2.z + N3 * w2.w;
    A.a3 += N0 * w3.x + N1 * w3.y + N2 * w3.z + N3 * w3.w;
}

// -----------------------------------------------------------------------------
// Main kernel: one block per 16x16 output tile (per batch). Each thread owns
// 1-2 input-halo pixels, accumulates over the 16-channel loop in registers,
// stores the 4 per-position planes F_e to smem, then gathers the output.
// -----------------------------------------------------------------------------
__global__ __launch_bounds__(256) void kan_main(const float* __restrict__ x,
                                                float* __restrict__ out) {
    __shared__ float sW[176];
    __shared__ float sF0[NPIX], sF1[NPIX], sF2[NPIX], sF3[NPIX];

    const int tid = threadIdx.x;
    if (tid < 176) sW[tid] = d_W[tid];

    const float g0   = d_grid0;
    const float invh = d_invh;
    const float bw0 = d_bw[0], bw1 = d_bw[1], bw2 = d_bw[2], bw3 = d_bw[3];

    const int b  = blockIdx.z;
    const int h0 = blockIdx.y * TH;
    const int w0 = blockIdx.x * TW;

    // Owned halo pixels (289 pixels, 256 threads -> threads 0..32 own a second)
    const int p0 = tid;
    const int p1 = tid + 256;
    const int r0 = p0 / IW, c0 = p0 % IW;
    const int r1 = p1 / IW, c1 = p1 % IW;
    const bool own1 = (p1 < NPIX);

    const int h_0 = h0 + r0, w_0 = w0 + c0;
    const int h_1 = h0 + r1, w_1 = w0 + c1;
    const bool inb0 = (h_0 < H_IN) && (w_0 < W_IN);
    const bool inb1 = own1 && (h_1 < H_IN) && (w_1 < W_IN);

    const float* __restrict__ xb = x + ((size_t)b * C_IN) * (H_IN * W_IN);
    const int off0 = h_0 * W_IN + w_0;
    const int off1 = h_1 * W_IN + w_1;

    Acc A0 = {0.f, 0.f, 0.f, 0.f, 0.f};
    Acc A1 = {0.f, 0.f, 0.f, 0.f, 0.f};

    __syncthreads();   // sW ready

    #pragma unroll 4
    for (int c = 0; c < C_IN; ++c) {
        const float* __restrict__ xc = xb + c * (H_IN * W_IN);
        float v0 = inb0 ? __ldg(xc + off0) : 0.0f;
        float v1 = inb1 ? __ldg(xc + off1) : 0.0f;
        eval_accum(v0, g0, invh, sW, A0);
        if (own1) eval_accum(v1, g0, invh, sW, A1);
    }

    // F_e(v) = bw_e * sum_c silu + sum_c spline_e   (per owned halo pixel)
    sF0[p0] = bw0 * A0.ss + A0.a0;
    sF1[p0] = bw1 * A0.ss + A0.a1;
    sF2[p0] = bw2 * A0.ss + A0.a2;
    sF3[p0] = bw3 * A0.ss + A0.a3;
    if (own1) {
        sF0[p1] = bw0 * A1.ss + A1.a0;
        sF1[p1] = bw1 * A1.ss + A1.a1;
        sF2[p1] = bw2 * A1.ss + A1.a2;
        sF3[p1] = bw3 * A1.ss + A1.a3;
    }
    __syncthreads();

    // Gather: out(r,c) = F0[r][c] + F1[r][c+1] + F2[r+1][c] + F3[r+1][c+1]
    const int r  = tid >> 4;   // 0..15
    const int cc = tid & 15;   // 0..15
    const int ho = h0 + r;
    const int wo = w0 + cc;
    if (ho < HO && wo < WO) {
        const int base = r * IW + cc;
        float val = sF0[base] + sF1[base + 1] + sF2[base + IW] + sF3[base + IW + 1];
        out[((size_t)b * HO + ho) * WO + wo] = val;
    }
}

// -----------------------------------------------------------------------------
// Launch. Inputs per metadata order: x, base_weight, spline_weight,
// spline_scaler, grid. Output: float32 (8,1,127,127).
// -----------------------------------------------------------------------------
extern "C" void kernel_launch(void* const* d_in, const int* in_sizes, int n_in,
                              void* d_out, int out_size) {
    const float* x    = (const float*)d_in[0];
    const float* bw   = (const float*)d_in[1];
    const float* sw   = (const float*)d_in[2];
    const float* sc   = (const float*)d_in[3];
    const float* grid = (const float*)d_in[4];
    float* out = (float*)d_out;

    kan_prep<<<1, 192>>>(bw, sw, sc, grid);

    dim3 g((WO + TW - 1) / TW, (HO + TH - 1) / TH, B_IN);  // 8 x 8 x 8
    kan_main<<<g, 256>>>(x, out);
}

// round 5
// speedup vs baseline: 1.2243x; 1.2243x over previous
#include <cuda_runtime.h>
#include <math.h>

// Problem constants (shapes fixed by the dataset)
#define B_IN  8
#define C_IN  16
#define H_IN  128
#define W_IN  128
#define HO    127
#define WO    127

// Tile geometry: 16x16 output tile -> 17x17 input halo
#define TW    16
#define TH    16
#define IW    17
#define NPIX  (IW * IW)   // 289

// Channel split: 4 blocks per tile, 4 channels each, atomicAdd partials
#define CH_SPLIT 4
#define CH_PER   4

// Poly table: 4 e-features x 12 intervals (row 11 = zeros for out-of-range)
// x 4 cubic coefficients (c0,c1,c2,c3), Horner in local fraction f.
#define P_ELEMS (4 * 12 * 4)   // 192 floats

__device__ float d_P[P_ELEMS];
__device__ float d_bw[4];
__device__ float d_grid0;
__device__ float d_invh;

// -----------------------------------------------------------------------------
// Prep: fold spline weights + cardinal cubic B-spline basis polynomials into
// per-interval cubics. On the uniform unclamped knot grid the Cox-de-Boor
// bases are the cardinal cubic translates:
//   N0=(1-3f+3f^2-f^3)/6, N1=(3f^3-6f^2+4)/6, N2=(-3f^3+3f^2+3f+1)/6, N3=f^3/6
// Reference drops basis indices outside [0,8) -> zero-padded W, and interval
// row 11 is all-zero (out-of-range sentinel).
// -----------------------------------------------------------------------------
__global__ void kan_prep(const float* __restrict__ base_weight,
                         const float* __restrict__ spline_weight,
                         const float* __restrict__ spline_scaler,
                         const float* __restrict__ grid) {
    int t = threadIdx.x;
    if (t == 0) {
        d_grid0 = grid[0];
        d_invh  = 1.0f / (grid[1] - grid[0]);
    }
    if (t < 4) d_bw[t] = base_weight[t];
    if (t < P_ELEMS) {
        int k = t & 3;            // coeff index
        int i = (t >> 2) % 12;    // interval 0..11
        int e = t / 48;           // out-feature 0..3
        float W[4];
        #pragma unroll
        for (int m = 0; m < 4; ++m) {
            int j = i - 3 + m;    // global basis index
            W[m] = (i < 11 && j >= 0 && j < 8)
                 ? spline_weight[e * 8 + j] * spline_scaler[e] : 0.0f;
        }
        float c;
        switch (k) {
            case 0:  c = (W[0] + 4.0f * W[1] + W[2]) * (1.0f / 6.0f); break;
            case 1:  c = 0.5f * (W[2] - W[0]); break;
            case 2:  c = 0.5f * (W[0] + W[2]) - W[1]; break;
            default: c = (-W[0] + 3.0f * W[1] - 3.0f * W[2] + W[3]) * (1.0f / 6.0f); break;
        }
        d_P[t] = c;
    }
}

// -----------------------------------------------------------------------------
// Per-value evaluation: silu-sum + 4 Horner cubics (one per out-feature e).
// -----------------------------------------------------------------------------
struct Acc {
    float ss;
    float a0, a1, a2, a3;
};

__device__ __forceinline__ void eval_accum(float v, float g0, float invh,
                                           const float* __restrict__ sP, Acc& A) {
    // SiLU
    float ex = __expf(-v);
    A.ss += __fdividef(v, 1.0f + ex);

    // Interval + local fraction on the uniform grid
    float u  = (v - g0) * invh;
    float fi = floorf(u);
    float f  = u - fi;
    int   i  = (int)fi;
    if (!((u >= 0.0f) && (u < 11.0f))) i = 11;   // zero row

    // sP layout: [e][i] float4, e-stride 48 words, i-stride 4 words
    const float4 p0 = *reinterpret_cast<const float4*>(sP +   0 + i * 4);
    const float4 p1 = *reinterpret_cast<const float4*>(sP +  48 + i * 4);
    const float4 p2 = *reinterpret_cast<const float4*>(sP +  96 + i * 4);
    const float4 p3 = *reinterpret_cast<const float4*>(sP + 144 + i * 4);
    A.a0 += p0.x + f * (p0.y + f * (p0.z + f * p0.w));
    A.a1 += p1.x + f * (p1.y + f * (p1.z + f * p1.w));
    A.a2 += p2.x + f * (p2.y + f * (p2.z + f * p2.w));
    A.a3 += p3.x + f * (p3.y + f * (p3.z + f * p3.w));
}

// -----------------------------------------------------------------------------
// Main kernel: one block per (16x16 output tile, batch, channel-quarter).
// Each thread owns 1-2 halo pixels, accumulates over its 4 channels in
// registers, stores the 4 per-position planes to smem, gathers the partial
// output and atomicAdds it.
// -----------------------------------------------------------------------------
__global__ __launch_bounds__(256, 6) void kan_main(const float* __restrict__ x,
                                                   float* __restrict__ out) {
    __shared__ float sP[P_ELEMS];
    __shared__ float sF0[NPIX], sF1[NPIX], sF2[NPIX], sF3[NPIX];

    const int tid = threadIdx.x;
    if (tid < P_ELEMS) sP[tid] = d_P[tid];

    const float g0   = d_grid0;
    const float invh = d_invh;
    const float bw0 = d_bw[0], bw1 = d_bw[1], bw2 = d_bw[2], bw3 = d_bw[3];

    const int bz = blockIdx.z;
    const int b  = bz >> 2;          // batch
    const int sp = bz & 3;           // channel quarter
    const int h0 = blockIdx.y * TH;
    const int w0 = blockIdx.x * TW;

    // Owned halo pixels (289 pixels, 256 threads -> threads 0..32 own a second)
    const int p0 = tid;
    const int p1 = tid + 256;
    const int r0 = p0 / IW, c0 = p0 % IW;
    const int r1 = p1 / IW, c1 = p1 % IW;
    const bool own1 = (p1 < NPIX);

    const int h_0 = h0 + r0, w_0 = w0 + c0;
    const int h_1 = h0 + r1, w_1 = w0 + c1;
    const bool inb0 = (h_0 < H_IN) && (w_0 < W_IN);
    const bool inb1 = own1 && (h_1 < H_IN) && (w_1 < W_IN);

    const float* __restrict__ xb =
        x + ((size_t)b * C_IN + sp * CH_PER) * (H_IN * W_IN);
    const int off0 = h_0 * W_IN + w_0;
    const int off1 = h_1 * W_IN + w_1;

    Acc A0 = {0.f, 0.f, 0.f, 0.f, 0.f};
    Acc A1 = {0.f, 0.f, 0.f, 0.f, 0.f};

    __syncthreads();   // sP ready

    #pragma unroll
    for (int c = 0; c < CH_PER; ++c) {
        const float* __restrict__ xc = xb + c * (H_IN * W_IN);
        float v0 = inb0 ? __ldg(xc + off0) : 0.0f;
        float v1 = inb1 ? __ldg(xc + off1) : 0.0f;
        eval_accum(v0, g0, invh, sP, A0);
        if (own1) eval_accum(v1, g0, invh, sP, A1);
    }

    // F_e(v) = bw_e * sum_c silu + sum_c spline_e  (partial over this quarter)
    sF0[p0] = bw0 * A0.ss + A0.a0;
    sF1[p0] = bw1 * A0.ss + A0.a1;
    sF2[p0] = bw2 * A0.ss + A0.a2;
    sF3[p0] = bw3 * A0.ss + A0.a3;
    if (own1) {
        sF0[p1] = bw0 * A1.ss + A1.a0;
        sF1[p1] = bw1 * A1.ss + A1.a1;
        sF2[p1] = bw2 * A1.ss + A1.a2;
        sF3[p1] = bw3 * A1.ss + A1.a3;
    }
    __syncthreads();

    // Gather: out(r,c) += F0[r][c] + F1[r][c+1] + F2[r+1][c] + F3[r+1][c+1]
    const int r  = tid >> 4;   // 0..15
    const int cc = tid & 15;   // 0..15
    const int ho = h0 + r;
    const int wo = w0 + cc;
    if (ho < HO && wo < WO) {
        const int base = r * IW + cc;
        float val = sF0[base] + sF1[base + 1] + sF2[base + IW] + sF3[base + IW + 1];
        atomicAdd(&out[((size_t)b * HO + ho) * WO + wo], val);
    }
}

// -----------------------------------------------------------------------------
// Launch. Inputs per metadata order: x, base_weight, spline_weight,
// spline_scaler, grid. Output: float32 (8,1,127,127), accumulated atomically
// over 4 channel-quarters after an async zero-init.
// -----------------------------------------------------------------------------
extern "C" void kernel_launch(void* const* d_in, const int* in_sizes, int n_in,
                              void* d_out, int out_size) {
    const float* x    = (const float*)d_in[0];
    const float* bw   = (const float*)d_in[1];
    const float* sw   = (const float*)d_in[2];
    const float* sc   = (const float*)d_in[3];
    const float* grid = (const float*)d_in[4];
    float* out = (float*)d_out;

    cudaMemsetAsync(out, 0, (size_t)out_size * sizeof(float));
    kan_prep<<<1, P_ELEMS>>>(bw, sw, sc, grid);

    dim3 g((WO + TW - 1) / TW, (HO + TH - 1) / TH, B_IN * CH_SPLIT);  // 8 x 8 x 32
    kan_main<<<g, 256>>>(x, out);
}